// round 15
// baseline (speedup 1.0000x reference)
#include <cuda_runtime.h>
#include <cuda_bf16.h>
#include <cuda_fp16.h>
#include <math.h>
#include <stdint.h>

#define NB     8
#define CFEAT  384
#define CCODE  90
#define CPAD   96
#define HH     56
#define WW     56
#define SSD    32
#define SP     1024
#define NCOMBO 40
#define HWIMG  3136
#define KTOT   576         // 384 feats (f16 1-term) + 192 code (f16 2-term)
#define KOFF_C 384
#define NSTAGE 18          // K32 chunks over KTOT
#define FSTAGE 12          // chunks 0..11 feats, 12..17 code
#define SROW   40          // smem row stride in f16 -> conflict-free frags
#define NTILE  3072        // gemm grid size (8*8*48)

#define STAGE_BYTES (2*128*SROW*2)               // A+B per stage = 20480 B
#define FD_OFF      (2*STAGE_BYTES)              // 40960
#define GEMM_DSMEM  (FD_OFF + 256*64*4)          // + fd spill 65536 -> 106496 B

// ---------------- scratch ----------------
__device__ float g_featsT[NB][HWIMG*CFEAT];
__device__ float g_codeT[NB][HWIMG*CPAD];
__device__ __align__(256) __half g_A [NB][SP*KTOT];
__device__ __align__(256) __half g_BB[NB][SP*KTOT];
__device__ __align__(256) __half g_B2[NCOMBO][SP*KTOT];
__device__ float g_E1[NB][SP];
__device__ float g_E2[NCOMBO][SP];
__device__ double g_acc[2];
__device__ int g_done;

// ---------------- ptx helpers ----------------
__device__ __forceinline__ void cp16(void* sm, const void* gm) {
    unsigned a = (unsigned)__cvta_generic_to_shared(sm);
    asm volatile("cp.async.cg.shared.global [%0], [%1], 16;\n" :: "r"(a), "l"(gm));
}
__device__ __forceinline__ void cp_commit() { asm volatile("cp.async.commit_group;\n"); }
__device__ __forceinline__ void cp_wait1()  { asm volatile("cp.async.wait_group 1;\n"); }
__device__ __forceinline__ void cp_wait0()  { asm volatile("cp.async.wait_group 0;\n"); }

__device__ __forceinline__ void ldsm4(uint32_t* r, uint32_t addr) {
    asm volatile("ldmatrix.sync.aligned.m8n8.x4.shared.b16 {%0,%1,%2,%3}, [%4];"
        : "=r"(r[0]), "=r"(r[1]), "=r"(r[2]), "=r"(r[3]) : "r"(addr));
}

__device__ __forceinline__ void mma_f16(float* d, uint32_t a0, uint32_t a1, uint32_t a2, uint32_t a3,
                                        uint32_t b0, uint32_t b1) {
    asm volatile(
        "mma.sync.aligned.m16n8k16.row.col.f32.f16.f16.f32 "
        "{%0,%1,%2,%3},{%4,%5,%6,%7},{%8,%9},{%0,%1,%2,%3};\n"
        : "+f"(d[0]), "+f"(d[1]), "+f"(d[2]), "+f"(d[3])
        : "r"(a0), "r"(a1), "r"(a2), "r"(a3), "r"(b0), "r"(b1));
}

// ---------------- merged transpose (float4 both sides): [c][p] -> [p][c] ----------------
// blockDim (8,32): tx = p-quad, ty = c. cz<12: feats, cz>=12: code.
__global__ void k_tpose(const float* __restrict__ feats, const float* __restrict__ code) {
    __shared__ __align__(16) float tile[32][36];   // [p_local][c_local]
    int n = blockIdx.x, pz = blockIdx.y, cz = blockIdx.z;
    int tx = threadIdx.x, ty = threadIdx.y;
    if (n == 0 && pz == 0 && cz == 0 && tx == 0 && ty == 0) {
        g_acc[0] = 0.0; g_acc[1] = 0.0; g_done = 0;
    }
    if (cz < 12) {
        const float* src = feats + (size_t)n*CFEAT*HWIMG;
        int c = cz*32 + ty;
        float4 v = *(const float4*)(src + (size_t)c*HWIMG + pz*32 + tx*4);
        tile[tx*4+0][ty] = v.x; tile[tx*4+1][ty] = v.y;
        tile[tx*4+2][ty] = v.z; tile[tx*4+3][ty] = v.w;
        __syncthreads();
        float* dst = g_featsT[n];
        int p = pz*32 + ty;
        *(float4*)(dst + (size_t)p*CFEAT + cz*32 + tx*4) = *(const float4*)&tile[ty][tx*4];
    } else {
        int czc = cz - 12;
        const float* src = code + (size_t)n*CCODE*HWIMG;
        int c = czc*32 + ty;
        float4 v = make_float4(0.f, 0.f, 0.f, 0.f);
        if (c < CCODE) v = *(const float4*)(src + (size_t)c*HWIMG + pz*32 + tx*4);
        tile[tx*4+0][ty] = v.x; tile[tx*4+1][ty] = v.y;
        tile[tx*4+2][ty] = v.z; tile[tx*4+3][ty] = v.w;
        __syncthreads();
        float* dst = g_codeT[n];
        int p = pz*32 + ty;
        *(float4*)(dst + (size_t)p*CPAD + czc*32 + tx*4) = *(const float4*)&tile[ty][tx*4];
    }
}

// ---------------- bilinear + sampling ----------------
struct BI { int o00,o01,o10,o11; float w00,w01,w10,w11; };

__device__ __forceinline__ BI bilinear(const float* __restrict__ crd) {
    float gx = (crd[0] + 1.0f) * 0.5f * (float)(WW-1);
    float gy = (crd[1] + 1.0f) * 0.5f * (float)(HH-1);
    gx = fminf(fmaxf(gx, 0.0f), (float)(WW-1));
    gy = fminf(fmaxf(gy, 0.0f), (float)(HH-1));
    float x0f = floorf(gx), y0f = floorf(gy);
    float wx = gx - x0f,   wy = gy - y0f;
    int x0 = (int)x0f, y0 = (int)y0f;
    int x1 = min(x0+1, WW-1), y1 = min(y0+1, HH-1);
    BI b;
    b.o00 = y0*WW + x0; b.o01 = y0*WW + x1;
    b.o10 = y1*WW + x0; b.o11 = y1*WW + x1;
    b.w00 = (1.0f-wx)*(1.0f-wy); b.w01 = wx*(1.0f-wy);
    b.w10 = (1.0f-wx)*wy;        b.w11 = wx*wy;
    return b;
}

__device__ __forceinline__ uint32_t pack_h2(float lo, float hi) {
    __half2 t = __floats2half2_rn(lo, hi);
    return *(uint32_t*)&t;
}
__device__ __forceinline__ float h_hi_f(float v) {
    return __half2float(__float2half_rn(v));
}
__device__ __forceinline__ void st2(__half* p, int off, uint32_t v) {
    *(uint32_t*)(p + off) = v;
}

__device__ __forceinline__ void sample_warp(
    int img, const float* __restrict__ crd, int lane,
    __half* __restrict__ rowA,   // may be null
    __half* __restrict__ rowB,
    float* __restrict__ entOut)
{
    BI bi = bilinear(crd);
    const float* T = g_featsT[img];
    const float4* p00 = (const float4*)(T + (size_t)bi.o00*CFEAT);
    const float4* p01 = (const float4*)(T + (size_t)bi.o01*CFEAT);
    const float4* p10 = (const float4*)(T + (size_t)bi.o10*CFEAT);
    const float4* p11 = (const float4*)(T + (size_t)bi.o11*CFEAT);

    float4 v[3]; float ss = 0.0f;
    #pragma unroll
    for (int j = 0; j < 3; ++j) {
        int cq = lane + 32*j;                // float4 index; c = 4*cq
        float4 a = p00[cq], b = p01[cq], c4 = p10[cq], d4 = p11[cq];
        float4 r;
        r.x = bi.w00*a.x + bi.w01*b.x + bi.w10*c4.x + bi.w11*d4.x;
        r.y = bi.w00*a.y + bi.w01*b.y + bi.w10*c4.y + bi.w11*d4.y;
        r.z = bi.w00*a.z + bi.w01*b.z + bi.w10*c4.z + bi.w11*d4.z;
        r.w = bi.w00*a.w + bi.w01*b.w + bi.w10*c4.w + bi.w11*d4.w;
        v[j] = r;
        ss += r.x*r.x + r.y*r.y + r.z*r.z + r.w*r.w;
    }
    #pragma unroll
    for (int o = 16; o; o >>= 1) ss += __shfl_xor_sync(0xffffffffu, ss, o);
    float sc = 1.0f / fmaxf(sqrtf(ss), 1e-10f);

    // feats: single fp16 term, 8B packed stores
    #pragma unroll
    for (int j = 0; j < 3; ++j) {
        int c = 4*(lane + 32*j);
        uint2 hp;
        hp.x = pack_h2(v[j].x*sc, v[j].y*sc);
        hp.y = pack_h2(v[j].z*sc, v[j].w*sc);
        if (rowA) *(uint2*)(rowA + c) = hp;
        *(uint2*)(rowB + c) = hp;
    }

    const float* C = g_codeT[img];
    const float* q00 = C + (size_t)bi.o00*CPAD;
    const float* q01 = C + (size_t)bi.o01*CPAD;
    const float* q10 = C + (size_t)bi.o10*CPAD;
    const float* q11 = C + (size_t)bi.o11*CPAD;
    float r0[2], r1[2];
    #pragma unroll
    for (int j = 0; j < 2; ++j) {
        int c = 2*lane + 64*j;
        bool ok = (c < CCODE);
        r0[j] = ok ? (bi.w00*q00[c]   + bi.w01*q01[c]   + bi.w10*q10[c]   + bi.w11*q11[c])   : -INFINITY;
        r1[j] = ok ? (bi.w00*q00[c+1] + bi.w01*q01[c+1] + bi.w10*q10[c+1] + bi.w11*q11[c+1]) : -INFINITY;
    }
    float m = fmaxf(fmaxf(r0[0], r1[0]), fmaxf(r0[1], r1[1]));
    #pragma unroll
    for (int o = 16; o; o >>= 1) m = fmaxf(m, __shfl_xor_sync(0xffffffffu, m, o));
    float se = 0.0f;
    #pragma unroll
    for (int j = 0; j < 2; ++j) se += expf(r0[j] - m) + expf(r1[j] - m);
    #pragma unroll
    for (int o = 16; o; o >>= 1) se += __shfl_xor_sync(0xffffffffu, se, o);
    float ls = m + logf(se);

    // code 2-term: A = [lh | ll], B = [qh | qh]
    float ent = 0.0f;
    #pragma unroll
    for (int j = 0; j < 2; ++j) {
        int c = 2*lane + 64*j;
        if (c < CPAD) {
            uint32_t lhp = 0, llp = 0, qhp = 0;
            if (c < CCODE) {
                float lp0 = r0[j] - ls, lp1 = r1[j] - ls;
                float q0 = expf(lp0),  q1 = expf(lp1);
                ent += q0*lp0 + q1*lp1;
                float lh0 = h_hi_f(lp0), lh1 = h_hi_f(lp1);
                lhp = pack_h2(lp0, lp1);
                llp = pack_h2(lp0 - lh0, lp1 - lh1);
                qhp = pack_h2(q0, q1);
            }
            if (rowA) { st2(rowA, KOFF_C+c, lhp); st2(rowA, KOFF_C+CPAD+c, llp); }
            st2(rowB, KOFF_C+c, qhp); st2(rowB, KOFF_C+CPAD+c, qhp);
        }
    }
    #pragma unroll
    for (int o = 16; o; o >>= 1) ent += __shfl_xor_sync(0xffffffffu, ent, o);
    if (lane == 0) *entOut = ent;
}

__global__ void __launch_bounds__(256) k_sample(const float* __restrict__ coords1,
                                                const float* __restrict__ coords2,
                                                const int* __restrict__ perms) {
    int x = blockIdx.x;
    int warp = threadIdx.x >> 5, lane = threadIdx.x & 31;
    int s = blockIdx.y * 8 + warp;
    int a = s >> 5, b = s & 31;
    if (x < 8) {
        int n = x;
        const float* crd = coords1 + (((n*SSD + b)*SSD + a) << 1);
        sample_warp(n, crd, lane,
                    g_A[n]  + (size_t)s*KTOT,
                    g_BB[n] + (size_t)s*KTOT,
                    &g_E1[n][s]);
    } else {
        int combo = x - 8;
        int i = combo & 7;
        int p = perms[combo];
        const float* crd = coords2 + (((i*SSD + b)*SSD + a) << 1);
        sample_warp(p, crd, lane,
                    (__half*)nullptr,
                    g_B2[combo] + (size_t)s*KTOT,
                    &g_E2[combo][s]);
    }
}

// ---------------- fused dual-GEMM + loss + last-block finalize ----------------
typedef __half (*Stage)[SROW];

__device__ __forceinline__ void load_stage(Stage sA, Stage sB,
                                           const __half* Ag, const __half* Bg,
                                           int k0, int tid) {
    #pragma unroll
    for (int j = 0; j < 2; ++j) {
        int chunk = tid + j*256;
        int row = chunk >> 2, q = chunk & 3;
        cp16(&sA[row][q*8], Ag + (size_t)row*KTOT + k0 + q*8);
        cp16(&sB[row][q*8], Bg + (size_t)row*KTOT + k0 + q*8);
    }
    cp_commit();
}

__device__ __forceinline__ void compute_chunk(float (*acc)[8][4],
                                              Stage sA, Stage sB,
                                              int wm, int wn, int lane) {
    int l7 = lane & 7, j = lane >> 3;
    int rAoff = ((j & 1) << 3) + l7;
    int kA8   = (j >> 1) << 3;
    int rBoff = ((j >> 1) << 3) + l7;
    int kB8   = (j & 1) << 3;
    #pragma unroll
    for (int kk = 0; kk < 32; kk += 16) {
        uint32_t a[2][4];
        #pragma unroll
        for (int mi = 0; mi < 2; ++mi) {
            uint32_t ad = (uint32_t)__cvta_generic_to_shared(&sA[wm + mi*16 + rAoff][kk + kA8]);
            ldsm4(a[mi], ad);
        }
        #pragma unroll
        for (int p = 0; p < 4; ++p) {
            uint32_t bd = (uint32_t)__cvta_generic_to_shared(&sB[wn + p*16 + rBoff][kk + kB8]);
            uint32_t bb[4];
            ldsm4(bb, bd);
            mma_f16(acc[0][2*p  ], a[0][0], a[0][1], a[0][2], a[0][3], bb[0], bb[1]);
            mma_f16(acc[0][2*p+1], a[0][0], a[0][1], a[0][2], a[0][3], bb[2], bb[3]);
            mma_f16(acc[1][2*p  ], a[1][0], a[1][1], a[1][2], a[1][3], bb[0], bb[1]);
            mma_f16(acc[1][2*p+1], a[1][0], a[1][1], a[1][2], a[1][3], bb[2], bb[3]);
        }
    }
}

__global__ void __launch_bounds__(256, 2) k_gemm(float* __restrict__ out) {
    extern __shared__ char dyn[];
    __shared__ float sh_ent[128];
    __shared__ float red[8];

    Stage sA[2], sB[2];
    #pragma unroll
    for (int b = 0; b < 2; ++b) {
        sA[b] = (Stage)(dyn + (size_t)b*STAGE_BYTES);
        sB[b] = (Stage)(dyn + (size_t)b*STAGE_BYTES + 128*SROW*2);
    }
    float* fd_s = (float*)(dyn + FD_OFF);     // [64][256] thread-private slots

    int tid = threadIdx.x;
    int warp = tid >> 5, lane = tid & 31;
    int pair = blockIdx.z;
    const __half *Apt, *Bpt; const float* ent;
    if (pair < 8) { Apt = g_A[pair];  Bpt = g_BB[pair]; ent = g_E1[pair]; }
    else { int c = pair - 8, i = c & 7; Apt = g_A[i]; Bpt = g_B2[c]; ent = g_E2[c]; }
    int m0 = blockIdx.x * 128, n0 = blockIdx.y * 128;
    const __half* Ag = Apt + (size_t)m0*KTOT;
    const __half* Bg = Bpt + (size_t)n0*KTOT;

    if (tid < 128) sh_ent[tid] = ent[n0 + tid];

    int wm = (warp & 3) * 32;
    int wn = (warp >> 2) * 64;
    int tg = lane & 3;

    float acc[2][8][4] = {};

    load_stage(sA[0], sB[0], Ag, Bg, 0, tid);
    for (int st = 0; st < NSTAGE; ++st) {
        if (st + 1 < NSTAGE) { load_stage(sA[(st+1)&1], sB[(st+1)&1], Ag, Bg, (st+1)*32, tid); cp_wait1(); }
        else                 { cp_wait0(); }
        __syncthreads();
        compute_chunk(acc, sA[st&1], sB[st&1], wm, wn, lane);
        if (st == FSTAGE - 1) {              // fd complete: spill to private smem slots
            #pragma unroll
            for (int mi = 0; mi < 2; ++mi)
                #pragma unroll
                for (int ni = 0; ni < 8; ++ni)
                    #pragma unroll
                    for (int r = 0; r < 4; ++r) {
                        fd_s[(((mi*8 + ni)<<2) + r)*256 + tid] = acc[mi][ni][r];
                        acc[mi][ni][r] = 0.0f;
                    }
        }
        __syncthreads();
    }

    // epilogue: acc = cr, fd from smem
    float lsum = 0.0f;
    #pragma unroll
    for (int ni = 0; ni < 8; ++ni) {
        float e0 = sh_ent[wn + ni*8 + 2*tg], e1 = sh_ent[wn + ni*8 + 2*tg + 1];
        #pragma unroll
        for (int mi = 0; mi < 2; ++mi) {
            #pragma unroll
            for (int r = 0; r < 4; ++r) {
                float e  = (r & 1) ? e1 : e0;
                float fd = fd_s[(((mi*8 + ni)<<2) + r)*256 + tid];
                float t = e - acc[mi][ni][r] - 1.1f;
                t = fminf(fmaxf(t, -30.0f), 30.0f);
                float u  = __expf(t);
                float th = __fdividef(u - 1.0f, u + 1.0f);   // tanh(t/2)
                float d  = fd + th;
                lsum += d * d;
            }
        }
    }

    #pragma unroll
    for (int off = 16; off > 0; off >>= 1)
        lsum += __shfl_down_sync(0xffffffffu, lsum, off);
    if (lane == 0) red[warp] = lsum;
    __syncthreads();
    if (tid == 0) {
        float tot = 0.0f;
        #pragma unroll
        for (int w = 0; w < 8; ++w) tot += red[w];
        atomicAdd(&g_acc[pair < 8 ? 0 : 1], (double)tot);
        __threadfence();
        int ticket = atomicAdd(&g_done, 1);
        if (ticket == NTILE - 1) {           // last CTA: finalize
            out[0] = (float)(g_acc[0] / 8388608.0);     // 8  * 1024 * 1024
            out[1] = (float)(g_acc[1] / 41943040.0);    // 40 * 1024 * 1024
            g_done = 0;
        }
    }
}

// ---------------- launch ----------------
extern "C" void kernel_launch(void* const* d_in, const int* in_sizes, int n_in,
                              void* d_out, int out_size) {
    const float* feats   = (const float*)d_in[0];
    const float* code    = (const float*)d_in[1];
    const float* coords1 = (const float*)d_in[2];
    const float* coords2 = (const float*)d_in[3];
    const int*   perms   = (const int*)  d_in[4];
    float* out = (float*)d_out;

    cudaFuncSetAttribute(k_gemm, cudaFuncAttributeMaxDynamicSharedMemorySize, GEMM_DSMEM);

    k_tpose <<<dim3(NB, 98, 15), dim3(8, 32)>>>(feats, code);
    k_sample<<<dim3(48, 128), 256>>>(coords1, coords2, perms);
    k_gemm  <<<dim3(8, 8, 48), 256, GEMM_DSMEM>>>(out);
}

// round 16
// speedup vs baseline: 1.0577x; 1.0577x over previous
#include <cuda_runtime.h>
#include <cuda_bf16.h>
#include <cuda_fp16.h>
#include <math.h>
#include <stdint.h>

#define NB     8
#define CFEAT  384
#define CCODE  90
#define CPAD   96
#define HH     56
#define WW     56
#define SSD    32
#define SP     1024
#define NCOMBO 40
#define HWIMG  3136
#define KTOT   576         // 384 feats (f16 1-term) + 192 code (f16 2-term)
#define KOFF_C 384
#define NSTAGE 18          // K32 chunks over KTOT
#define FSTAGE 12          // chunks 0..11 feats, 12..17 code
#define SROW   40          // smem row stride in f16 -> conflict-free frags
#define NTILE  3072        // 48 pairs x 8 x 8
#define GRID   296         // persistent: 2 CTAs x 148 SMs

#define STAGE_BYTES (2*128*SROW*2)               // A+B per stage = 20480 B
#define FD_OFF      (2*STAGE_BYTES)              // 40960
#define GEMM_DSMEM  (FD_OFF + 256*64*4)          // + fd spill 65536 -> 106496 B

// ---------------- scratch ----------------
__device__ float g_featsT[NB][HWIMG*CFEAT];
__device__ float g_codeT[NB][HWIMG*CPAD];
__device__ __align__(256) __half g_A [NB][SP*KTOT];
__device__ __align__(256) __half g_BB[NB][SP*KTOT];
__device__ __align__(256) __half g_B2[NCOMBO][SP*KTOT];
__device__ float g_E1[NB][SP];
__device__ float g_E2[NCOMBO][SP];
__device__ double g_acc[2];
__device__ int g_done;

// ---------------- ptx helpers ----------------
__device__ __forceinline__ void cp16(void* sm, const void* gm) {
    unsigned a = (unsigned)__cvta_generic_to_shared(sm);
    asm volatile("cp.async.cg.shared.global [%0], [%1], 16;\n" :: "r"(a), "l"(gm));
}
__device__ __forceinline__ void cp_commit() { asm volatile("cp.async.commit_group;\n"); }
__device__ __forceinline__ void cp_wait1()  { asm volatile("cp.async.wait_group 1;\n"); }
__device__ __forceinline__ void cp_wait0()  { asm volatile("cp.async.wait_group 0;\n"); }

__device__ __forceinline__ void ldsm4(uint32_t* r, uint32_t addr) {
    asm volatile("ldmatrix.sync.aligned.m8n8.x4.shared.b16 {%0,%1,%2,%3}, [%4];"
        : "=r"(r[0]), "=r"(r[1]), "=r"(r[2]), "=r"(r[3]) : "r"(addr));
}

__device__ __forceinline__ void mma_f16(float* d, uint32_t a0, uint32_t a1, uint32_t a2, uint32_t a3,
                                        uint32_t b0, uint32_t b1) {
    asm volatile(
        "mma.sync.aligned.m16n8k16.row.col.f32.f16.f16.f32 "
        "{%0,%1,%2,%3},{%4,%5,%6,%7},{%8,%9},{%0,%1,%2,%3};\n"
        : "+f"(d[0]), "+f"(d[1]), "+f"(d[2]), "+f"(d[3])
        : "r"(a0), "r"(a1), "r"(a2), "r"(a3), "r"(b0), "r"(b1));
}

// ---------------- merged transpose (float4 both sides): [c][p] -> [p][c] ----------------
__global__ void k_tpose(const float* __restrict__ feats, const float* __restrict__ code) {
    __shared__ __align__(16) float tile[32][36];
    int n = blockIdx.x, pz = blockIdx.y, cz = blockIdx.z;
    int tx = threadIdx.x, ty = threadIdx.y;
    if (n == 0 && pz == 0 && cz == 0 && tx == 0 && ty == 0) {
        g_acc[0] = 0.0; g_acc[1] = 0.0; g_done = 0;
    }
    if (cz < 12) {
        const float* src = feats + (size_t)n*CFEAT*HWIMG;
        int c = cz*32 + ty;
        float4 v = *(const float4*)(src + (size_t)c*HWIMG + pz*32 + tx*4);
        tile[tx*4+0][ty] = v.x; tile[tx*4+1][ty] = v.y;
        tile[tx*4+2][ty] = v.z; tile[tx*4+3][ty] = v.w;
        __syncthreads();
        float* dst = g_featsT[n];
        int p = pz*32 + ty;
        *(float4*)(dst + (size_t)p*CFEAT + cz*32 + tx*4) = *(const float4*)&tile[ty][tx*4];
    } else {
        int czc = cz - 12;
        const float* src = code + (size_t)n*CCODE*HWIMG;
        int c = czc*32 + ty;
        float4 v = make_float4(0.f, 0.f, 0.f, 0.f);
        if (c < CCODE) v = *(const float4*)(src + (size_t)c*HWIMG + pz*32 + tx*4);
        tile[tx*4+0][ty] = v.x; tile[tx*4+1][ty] = v.y;
        tile[tx*4+2][ty] = v.z; tile[tx*4+3][ty] = v.w;
        __syncthreads();
        float* dst = g_codeT[n];
        int p = pz*32 + ty;
        *(float4*)(dst + (size_t)p*CPAD + czc*32 + tx*4) = *(const float4*)&tile[ty][tx*4];
    }
}

// ---------------- bilinear + sampling ----------------
struct BI { int o00,o01,o10,o11; float w00,w01,w10,w11; };

__device__ __forceinline__ BI bilinear(const float* __restrict__ crd) {
    float gx = (crd[0] + 1.0f) * 0.5f * (float)(WW-1);
    float gy = (crd[1] + 1.0f) * 0.5f * (float)(HH-1);
    gx = fminf(fmaxf(gx, 0.0f), (float)(WW-1));
    gy = fminf(fmaxf(gy, 0.0f), (float)(HH-1));
    float x0f = floorf(gx), y0f = floorf(gy);
    float wx = gx - x0f,   wy = gy - y0f;
    int x0 = (int)x0f, y0 = (int)y0f;
    int x1 = min(x0+1, WW-1), y1 = min(y0+1, HH-1);
    BI b;
    b.o00 = y0*WW + x0; b.o01 = y0*WW + x1;
    b.o10 = y1*WW + x0; b.o11 = y1*WW + x1;
    b.w00 = (1.0f-wx)*(1.0f-wy); b.w01 = wx*(1.0f-wy);
    b.w10 = (1.0f-wx)*wy;        b.w11 = wx*wy;
    return b;
}

__device__ __forceinline__ uint32_t pack_h2(float lo, float hi) {
    __half2 t = __floats2half2_rn(lo, hi);
    return *(uint32_t*)&t;
}
__device__ __forceinline__ float h_hi_f(float v) {
    return __half2float(__float2half_rn(v));
}
__device__ __forceinline__ void st2(__half* p, int off, uint32_t v) {
    *(uint32_t*)(p + off) = v;
}

__device__ __forceinline__ void sample_warp(
    int img, const float* __restrict__ crd, int lane,
    __half* __restrict__ rowA,   // may be null
    __half* __restrict__ rowB,
    float* __restrict__ entOut)
{
    BI bi = bilinear(crd);
    const float* T = g_featsT[img];
    const float4* p00 = (const float4*)(T + (size_t)bi.o00*CFEAT);
    const float4* p01 = (const float4*)(T + (size_t)bi.o01*CFEAT);
    const float4* p10 = (const float4*)(T + (size_t)bi.o10*CFEAT);
    const float4* p11 = (const float4*)(T + (size_t)bi.o11*CFEAT);

    float4 v[3]; float ss = 0.0f;
    #pragma unroll
    for (int j = 0; j < 3; ++j) {
        int cq = lane + 32*j;
        float4 a = p00[cq], b = p01[cq], c4 = p10[cq], d4 = p11[cq];
        float4 r;
        r.x = bi.w00*a.x + bi.w01*b.x + bi.w10*c4.x + bi.w11*d4.x;
        r.y = bi.w00*a.y + bi.w01*b.y + bi.w10*c4.y + bi.w11*d4.y;
        r.z = bi.w00*a.z + bi.w01*b.z + bi.w10*c4.z + bi.w11*d4.z;
        r.w = bi.w00*a.w + bi.w01*b.w + bi.w10*c4.w + bi.w11*d4.w;
        v[j] = r;
        ss += r.x*r.x + r.y*r.y + r.z*r.z + r.w*r.w;
    }
    #pragma unroll
    for (int o = 16; o; o >>= 1) ss += __shfl_xor_sync(0xffffffffu, ss, o);
    float sc = 1.0f / fmaxf(sqrtf(ss), 1e-10f);

    #pragma unroll
    for (int j = 0; j < 3; ++j) {
        int c = 4*(lane + 32*j);
        uint2 hp;
        hp.x = pack_h2(v[j].x*sc, v[j].y*sc);
        hp.y = pack_h2(v[j].z*sc, v[j].w*sc);
        if (rowA) *(uint2*)(rowA + c) = hp;
        *(uint2*)(rowB + c) = hp;
    }

    const float* C = g_codeT[img];
    const float* q00 = C + (size_t)bi.o00*CPAD;
    const float* q01 = C + (size_t)bi.o01*CPAD;
    const float* q10 = C + (size_t)bi.o10*CPAD;
    const float* q11 = C + (size_t)bi.o11*CPAD;
    float r0[2], r1[2];
    #pragma unroll
    for (int j = 0; j < 2; ++j) {
        int c = 2*lane + 64*j;
        bool ok = (c < CCODE);
        r0[j] = ok ? (bi.w00*q00[c]   + bi.w01*q01[c]   + bi.w10*q10[c]   + bi.w11*q11[c])   : -INFINITY;
        r1[j] = ok ? (bi.w00*q00[c+1] + bi.w01*q01[c+1] + bi.w10*q10[c+1] + bi.w11*q11[c+1]) : -INFINITY;
    }
    float m = fmaxf(fmaxf(r0[0], r1[0]), fmaxf(r0[1], r1[1]));
    #pragma unroll
    for (int o = 16; o; o >>= 1) m = fmaxf(m, __shfl_xor_sync(0xffffffffu, m, o));
    float se = 0.0f;
    #pragma unroll
    for (int j = 0; j < 2; ++j) se += expf(r0[j] - m) + expf(r1[j] - m);
    #pragma unroll
    for (int o = 16; o; o >>= 1) se += __shfl_xor_sync(0xffffffffu, se, o);
    float ls = m + logf(se);

    float ent = 0.0f;
    #pragma unroll
    for (int j = 0; j < 2; ++j) {
        int c = 2*lane + 64*j;
        if (c < CPAD) {
            uint32_t lhp = 0, llp = 0, qhp = 0;
            if (c < CCODE) {
                float lp0 = r0[j] - ls, lp1 = r1[j] - ls;
                float q0 = expf(lp0),  q1 = expf(lp1);
                ent += q0*lp0 + q1*lp1;
                float lh0 = h_hi_f(lp0), lh1 = h_hi_f(lp1);
                lhp = pack_h2(lp0, lp1);
                llp = pack_h2(lp0 - lh0, lp1 - lh1);
                qhp = pack_h2(q0, q1);
            }
            if (rowA) { st2(rowA, KOFF_C+c, lhp); st2(rowA, KOFF_C+CPAD+c, llp); }
            st2(rowB, KOFF_C+c, qhp); st2(rowB, KOFF_C+CPAD+c, qhp);
        }
    }
    #pragma unroll
    for (int o = 16; o; o >>= 1) ent += __shfl_xor_sync(0xffffffffu, ent, o);
    if (lane == 0) *entOut = ent;
}

__global__ void __launch_bounds__(256) k_sample(const float* __restrict__ coords1,
                                                const float* __restrict__ coords2,
                                                const int* __restrict__ perms) {
    int x = blockIdx.x;
    int warp = threadIdx.x >> 5, lane = threadIdx.x & 31;
    int s = blockIdx.y * 8 + warp;
    int a = s >> 5, b = s & 31;
    if (x < 8) {
        int n = x;
        const float* crd = coords1 + (((n*SSD + b)*SSD + a) << 1);
        sample_warp(n, crd, lane,
                    g_A[n]  + (size_t)s*KTOT,
                    g_BB[n] + (size_t)s*KTOT,
                    &g_E1[n][s]);
    } else {
        int combo = x - 8;
        int i = combo & 7;
        int p = perms[combo];
        const float* crd = coords2 + (((i*SSD + b)*SSD + a) << 1);
        sample_warp(p, crd, lane,
                    (__half*)nullptr,
                    g_B2[combo] + (size_t)s*KTOT,
                    &g_E2[combo][s]);
    }
}

// ---------------- persistent fused dual-GEMM + loss + finalize ----------------
typedef __half (*Stage)[SROW];

__device__ __forceinline__ void load_stage(Stage sA, Stage sB,
                                           const __half* Ag, const __half* Bg,
                                           int k0, int tid) {
    #pragma unroll
    for (int j = 0; j < 2; ++j) {
        int chunk = tid + j*256;
        int row = chunk >> 2, q = chunk & 3;
        cp16(&sA[row][q*8], Ag + (size_t)row*KTOT + k0 + q*8);
        cp16(&sB[row][q*8], Bg + (size_t)row*KTOT + k0 + q*8);
    }
    cp_commit();
}

__device__ __forceinline__ void compute_chunk(float (*acc)[8][4],
                                              Stage sA, Stage sB,
                                              int wm, int wn, int lane) {
    int l7 = lane & 7, j = lane >> 3;
    int rAoff = ((j & 1) << 3) + l7;
    int kA8   = (j >> 1) << 3;
    int rBoff = ((j >> 1) << 3) + l7;
    int kB8   = (j & 1) << 3;
    #pragma unroll
    for (int kk = 0; kk < 32; kk += 16) {
        uint32_t a[2][4];
        #pragma unroll
        for (int mi = 0; mi < 2; ++mi) {
            uint32_t ad = (uint32_t)__cvta_generic_to_shared(&sA[wm + mi*16 + rAoff][kk + kA8]);
            ldsm4(a[mi], ad);
        }
        #pragma unroll
        for (int p = 0; p < 4; ++p) {
            uint32_t bd = (uint32_t)__cvta_generic_to_shared(&sB[wn + p*16 + rBoff][kk + kB8]);
            uint32_t bb[4];
            ldsm4(bb, bd);
            mma_f16(acc[0][2*p  ], a[0][0], a[0][1], a[0][2], a[0][3], bb[0], bb[1]);
            mma_f16(acc[0][2*p+1], a[0][0], a[0][1], a[0][2], a[0][3], bb[2], bb[3]);
            mma_f16(acc[1][2*p  ], a[1][0], a[1][1], a[1][2], a[1][3], bb[0], bb[1]);
            mma_f16(acc[1][2*p+1], a[1][0], a[1][1], a[1][2], a[1][3], bb[2], bb[3]);
        }
    }
}

__global__ void __launch_bounds__(256, 2) k_gemm(float* __restrict__ out) {
    extern __shared__ char dyn[];
    __shared__ float sh_ent[128];
    __shared__ float red[16];

    Stage sA[2], sB[2];
    #pragma unroll
    for (int b = 0; b < 2; ++b) {
        sA[b] = (Stage)(dyn + (size_t)b*STAGE_BYTES);
        sB[b] = (Stage)(dyn + (size_t)b*STAGE_BYTES + 128*SROW*2);
    }
    float* fd_s = (float*)(dyn + FD_OFF);     // [64][256] thread-private slots

    int tid = threadIdx.x;
    int warp = tid >> 5, lane = tid & 31;
    int wm = (warp & 3) * 32;
    int wn = (warp >> 2) * 64;
    int tg = lane & 3;

    float psum = 0.0f, nsum = 0.0f;

    for (int tile = blockIdx.x; tile < NTILE; tile += GRID) {
        int pair = tile >> 6;
        int rem  = tile & 63;
        int m0 = (rem >> 3) << 7;
        int n0 = (rem & 7) << 7;
        const __half *Apt, *Bpt; const float* ent;
        if (pair < 8) { Apt = g_A[pair];  Bpt = g_BB[pair]; ent = g_E1[pair]; }
        else { int c = pair - 8, i = c & 7; Apt = g_A[i]; Bpt = g_B2[c]; ent = g_E2[c]; }
        const __half* Ag = Apt + (size_t)m0*KTOT;
        const __half* Bg = Bpt + (size_t)n0*KTOT;

        __syncthreads();                      // sh_ent reuse guard (prev epilogue done)
        if (tid < 128) sh_ent[tid] = ent[n0 + tid];

        float acc[2][8][4] = {};
        load_stage(sA[0], sB[0], Ag, Bg, 0, tid);
        for (int st = 0; st < NSTAGE; ++st) {
            if (st + 1 < NSTAGE) { load_stage(sA[(st+1)&1], sB[(st+1)&1], Ag, Bg, (st+1)*32, tid); cp_wait1(); }
            else                 { cp_wait0(); }
            __syncthreads();
            compute_chunk(acc, sA[st&1], sB[st&1], wm, wn, lane);
            if (st == FSTAGE - 1) {           // fd complete: spill to private smem slots
                #pragma unroll
                for (int mi = 0; mi < 2; ++mi)
                    #pragma unroll
                    for (int ni = 0; ni < 8; ++ni)
                        #pragma unroll
                        for (int r = 0; r < 4; ++r) {
                            fd_s[(((mi*8 + ni)<<2) + r)*256 + tid] = acc[mi][ni][r];
                            acc[mi][ni][r] = 0.0f;
                        }
            }
            __syncthreads();
        }

        float lsum = 0.0f;
        #pragma unroll
        for (int ni = 0; ni < 8; ++ni) {
            float e0 = sh_ent[wn + ni*8 + 2*tg], e1 = sh_ent[wn + ni*8 + 2*tg + 1];
            #pragma unroll
            for (int mi = 0; mi < 2; ++mi) {
                #pragma unroll
                for (int r = 0; r < 4; ++r) {
                    float e  = (r & 1) ? e1 : e0;
                    float fd = fd_s[(((mi*8 + ni)<<2) + r)*256 + tid];
                    float t = e - acc[mi][ni][r] - 1.1f;
                    t = fminf(fmaxf(t, -30.0f), 30.0f);
                    float u  = __expf(t);
                    float th = __fdividef(u - 1.0f, u + 1.0f);   // tanh(t/2)
                    float d  = fd + th;
                    lsum += d * d;
                }
            }
        }
        if (pair < 8) psum += lsum; else nsum += lsum;
    }

    // one block-reduction + atomics per CTA
    #pragma unroll
    for (int off = 16; off > 0; off >>= 1) {
        psum += __shfl_down_sync(0xffffffffu, psum, off);
        nsum += __shfl_down_sync(0xffffffffu, nsum, off);
    }
    if (lane == 0) { red[warp] = psum; red[8 + warp] = nsum; }
    __syncthreads();
    if (tid == 0) {
        float tp = 0.0f, tn = 0.0f;
        #pragma unroll
        for (int w = 0; w < 8; ++w) { tp += red[w]; tn += red[8 + w]; }
        if (tp != 0.0f) atomicAdd(&g_acc[0], (double)tp);
        if (tn != 0.0f) atomicAdd(&g_acc[1], (double)tn);
        __threadfence();
        int ticket = atomicAdd(&g_done, 1);
        if (ticket == GRID - 1) {
            out[0] = (float)(g_acc[0] / 8388608.0);     // 8  * 1024 * 1024
            out[1] = (float)(g_acc[1] / 41943040.0);    // 40 * 1024 * 1024
            g_done = 0;
        }
    }
}

// ---------------- launch ----------------
extern "C" void kernel_launch(void* const* d_in, const int* in_sizes, int n_in,
                              void* d_out, int out_size) {
    const float* feats   = (const float*)d_in[0];
    const float* code    = (const float*)d_in[1];
    const float* coords1 = (const float*)d_in[2];
    const float* coords2 = (const float*)d_in[3];
    const int*   perms   = (const int*)  d_in[4];
    float* out = (float*)d_out;

    cudaFuncSetAttribute(k_gemm, cudaFuncAttributeMaxDynamicSharedMemorySize, GEMM_DSMEM);

    k_tpose <<<dim3(NB, 98, 15), dim3(8, 32)>>>(feats, code);
    k_sample<<<dim3(48, 128), 256>>>(coords1, coords2, perms);
    k_gemm  <<<GRID, 256, GEMM_DSMEM>>>(out);
}

// round 17
// speedup vs baseline: 1.0753x; 1.0167x over previous
#include <cuda_runtime.h>
#include <cuda_bf16.h>
#include <cuda_fp16.h>
#include <math.h>
#include <stdint.h>

#define NB     8
#define CFEAT  384
#define CCODE  90
#define CPAD   96
#define HH     56
#define WW     56
#define SSD    32
#define SP     1024
#define NCOMBO 40
#define HWIMG  3136
#define KTOT   576         // 384 feats (f16 1-term) + 192 code (f16 2-term)
#define KOFF_C 384
#define NSTAGE 18          // K32 chunks over KTOT
#define FSTAGE 12          // chunks 0..11 feats, 12..17 code
#define SROW   40          // smem row stride in f16 -> conflict-free frags
#define NTILE  3072        // 48 pairs x 8 x 8
#define GRID   296         // persistent: 2 CTAs x 148 SMs
#define NPZ    98          // pixel tiles (3136/32)

#define STAGE_BYTES (2*128*SROW*2)               // A+B per stage = 20480 B
#define FD_OFF      (2*STAGE_BYTES)              // 40960
#define GEMM_DSMEM  (FD_OFF + 256*64*4)          // + fd spill 65536 -> 106496 B

// ---------------- scratch ----------------
__device__ float g_featsT[NB][HWIMG*CFEAT];
__device__ float g_codeT[NB][HWIMG*CPAD];
__device__ __align__(256) __half g_A [NB][SP*KTOT];
__device__ __align__(256) __half g_BB[NB][SP*KTOT];
__device__ __align__(256) __half g_B2[NCOMBO][SP*KTOT];
__device__ float g_E1[NB][SP];
__device__ float g_E2[NCOMBO][SP];
__device__ double g_acc[2];
__device__ int g_done;

// ---------------- ptx helpers ----------------
__device__ __forceinline__ void cp16(void* sm, const void* gm) {
    unsigned a = (unsigned)__cvta_generic_to_shared(sm);
    asm volatile("cp.async.cg.shared.global [%0], [%1], 16;\n" :: "r"(a), "l"(gm));
}
__device__ __forceinline__ void cp_commit() { asm volatile("cp.async.commit_group;\n"); }
__device__ __forceinline__ void cp_wait1()  { asm volatile("cp.async.wait_group 1;\n"); }
__device__ __forceinline__ void cp_wait0()  { asm volatile("cp.async.wait_group 0;\n"); }

__device__ __forceinline__ void ldsm4(uint32_t* r, uint32_t addr) {
    asm volatile("ldmatrix.sync.aligned.m8n8.x4.shared.b16 {%0,%1,%2,%3}, [%4];"
        : "=r"(r[0]), "=r"(r[1]), "=r"(r[2]), "=r"(r[3]) : "r"(addr));
}

__device__ __forceinline__ void mma_f16(float* d, uint32_t a0, uint32_t a1, uint32_t a2, uint32_t a3,
                                        uint32_t b0, uint32_t b1) {
    asm volatile(
        "mma.sync.aligned.m16n8k16.row.col.f32.f16.f16.f32 "
        "{%0,%1,%2,%3},{%4,%5,%6,%7},{%8,%9},{%0,%1,%2,%3};\n"
        : "+f"(d[0]), "+f"(d[1]), "+f"(d[2]), "+f"(d[3])
        : "r"(a0), "r"(a1), "r"(a2), "r"(a3), "r"(b0), "r"(b1));
}

// ---------------- merged transpose, 4 tiles/block for MLP=4 ----------------
// blockDim (8,32): tx = quad index, ty = row. blockIdx.y covers 4 pz tiles.
__global__ void k_tpose(const float* __restrict__ feats, const float* __restrict__ code) {
    __shared__ __align__(16) float tile[4][32][36];
    int n = blockIdx.x, cz = blockIdx.z;
    int tx = threadIdx.x, ty = threadIdx.y;
    if (n == 0 && blockIdx.y == 0 && cz == 0 && tx == 0 && ty == 0) {
        g_acc[0] = 0.0; g_acc[1] = 0.0; g_done = 0;
    }
    int pz0 = blockIdx.y * 4;
    if (cz < 12) {
        const float* src = feats + (size_t)n*CFEAT*HWIMG;
        int c = cz*32 + ty;
        float4 v[4];
        #pragma unroll
        for (int t = 0; t < 4; ++t) {
            int pz = pz0 + t;
            v[t] = (pz < NPZ) ? *(const float4*)(src + (size_t)c*HWIMG + pz*32 + tx*4)
                              : make_float4(0.f,0.f,0.f,0.f);
        }
        #pragma unroll
        for (int t = 0; t < 4; ++t) {
            tile[t][tx*4+0][ty] = v[t].x; tile[t][tx*4+1][ty] = v[t].y;
            tile[t][tx*4+2][ty] = v[t].z; tile[t][tx*4+3][ty] = v[t].w;
        }
        __syncthreads();
        float* dst = g_featsT[n];
        #pragma unroll
        for (int t = 0; t < 4; ++t) {
            int pz = pz0 + t;
            if (pz < NPZ) {
                int p = pz*32 + ty;
                *(float4*)(dst + (size_t)p*CFEAT + cz*32 + tx*4) = *(const float4*)&tile[t][ty][tx*4];
            }
        }
    } else {
        int czc = cz - 12;
        const float* src = code + (size_t)n*CCODE*HWIMG;
        int c = czc*32 + ty;
        float4 v[4];
        #pragma unroll
        for (int t = 0; t < 4; ++t) {
            int pz = pz0 + t;
            v[t] = (c < CCODE && pz < NPZ)
                 ? *(const float4*)(src + (size_t)c*HWIMG + pz*32 + tx*4)
                 : make_float4(0.f,0.f,0.f,0.f);
        }
        #pragma unroll
        for (int t = 0; t < 4; ++t) {
            tile[t][tx*4+0][ty] = v[t].x; tile[t][tx*4+1][ty] = v[t].y;
            tile[t][tx*4+2][ty] = v[t].z; tile[t][tx*4+3][ty] = v[t].w;
        }
        __syncthreads();
        float* dst = g_codeT[n];
        #pragma unroll
        for (int t = 0; t < 4; ++t) {
            int pz = pz0 + t;
            if (pz < NPZ) {
                int p = pz*32 + ty;
                *(float4*)(dst + (size_t)p*CPAD + czc*32 + tx*4) = *(const float4*)&tile[t][ty][tx*4];
            }
        }
    }
}

// ---------------- bilinear + sampling ----------------
struct BI { int o00,o01,o10,o11; float w00,w01,w10,w11; };

__device__ __forceinline__ BI bilinear(const float* __restrict__ crd) {
    float gx = (crd[0] + 1.0f) * 0.5f * (float)(WW-1);
    float gy = (crd[1] + 1.0f) * 0.5f * (float)(HH-1);
    gx = fminf(fmaxf(gx, 0.0f), (float)(WW-1));
    gy = fminf(fmaxf(gy, 0.0f), (float)(HH-1));
    float x0f = floorf(gx), y0f = floorf(gy);
    float wx = gx - x0f,   wy = gy - y0f;
    int x0 = (int)x0f, y0 = (int)y0f;
    int x1 = min(x0+1, WW-1), y1 = min(y0+1, HH-1);
    BI b;
    b.o00 = y0*WW + x0; b.o01 = y0*WW + x1;
    b.o10 = y1*WW + x0; b.o11 = y1*WW + x1;
    b.w00 = (1.0f-wx)*(1.0f-wy); b.w01 = wx*(1.0f-wy);
    b.w10 = (1.0f-wx)*wy;        b.w11 = wx*wy;
    return b;
}

__device__ __forceinline__ uint32_t pack_h2(float lo, float hi) {
    __half2 t = __floats2half2_rn(lo, hi);
    return *(uint32_t*)&t;
}
__device__ __forceinline__ float h_hi_f(float v) {
    return __half2float(__float2half_rn(v));
}
__device__ __forceinline__ void st2(__half* p, int off, uint32_t v) {
    *(uint32_t*)(p + off) = v;
}

__device__ __forceinline__ void sample_warp(
    int img, const float* __restrict__ crd, int lane,
    __half* __restrict__ rowA,   // may be null
    __half* __restrict__ rowB,
    float* __restrict__ entOut)
{
    BI bi = bilinear(crd);
    const float* T = g_featsT[img];
    const float4* p00 = (const float4*)(T + (size_t)bi.o00*CFEAT);
    const float4* p01 = (const float4*)(T + (size_t)bi.o01*CFEAT);
    const float4* p10 = (const float4*)(T + (size_t)bi.o10*CFEAT);
    const float4* p11 = (const float4*)(T + (size_t)bi.o11*CFEAT);

    float4 v[3]; float ss = 0.0f;
    #pragma unroll
    for (int j = 0; j < 3; ++j) {
        int cq = lane + 32*j;
        float4 a = p00[cq], b = p01[cq], c4 = p10[cq], d4 = p11[cq];
        float4 r;
        r.x = bi.w00*a.x + bi.w01*b.x + bi.w10*c4.x + bi.w11*d4.x;
        r.y = bi.w00*a.y + bi.w01*b.y + bi.w10*c4.y + bi.w11*d4.y;
        r.z = bi.w00*a.z + bi.w01*b.z + bi.w10*c4.z + bi.w11*d4.z;
        r.w = bi.w00*a.w + bi.w01*b.w + bi.w10*c4.w + bi.w11*d4.w;
        v[j] = r;
        ss += r.x*r.x + r.y*r.y + r.z*r.z + r.w*r.w;
    }
    #pragma unroll
    for (int o = 16; o; o >>= 1) ss += __shfl_xor_sync(0xffffffffu, ss, o);
    float sc = 1.0f / fmaxf(sqrtf(ss), 1e-10f);

    #pragma unroll
    for (int j = 0; j < 3; ++j) {
        int c = 4*(lane + 32*j);
        uint2 hp;
        hp.x = pack_h2(v[j].x*sc, v[j].y*sc);
        hp.y = pack_h2(v[j].z*sc, v[j].w*sc);
        if (rowA) *(uint2*)(rowA + c) = hp;
        *(uint2*)(rowB + c) = hp;
    }

    const float* C = g_codeT[img];
    const float2* q00 = (const float2*)(C + (size_t)bi.o00*CPAD);
    const float2* q01 = (const float2*)(C + (size_t)bi.o01*CPAD);
    const float2* q10 = (const float2*)(C + (size_t)bi.o10*CPAD);
    const float2* q11 = (const float2*)(C + (size_t)bi.o11*CPAD);
    float r0[2], r1[2];
    #pragma unroll
    for (int j = 0; j < 2; ++j) {
        int c = 2*lane + 64*j;                 // pair index c/2
        if (c < CCODE) {
            int cp = c >> 1;
            float2 a = q00[cp], b = q01[cp], c2 = q10[cp], d2 = q11[cp];
            r0[j] = bi.w00*a.x + bi.w01*b.x + bi.w10*c2.x + bi.w11*d2.x;
            r1[j] = bi.w00*a.y + bi.w01*b.y + bi.w10*c2.y + bi.w11*d2.y;
        } else { r0[j] = -INFINITY; r1[j] = -INFINITY; }
    }
    float m = fmaxf(fmaxf(r0[0], r1[0]), fmaxf(r0[1], r1[1]));
    #pragma unroll
    for (int o = 16; o; o >>= 1) m = fmaxf(m, __shfl_xor_sync(0xffffffffu, m, o));
    float se = 0.0f;
    #pragma unroll
    for (int j = 0; j < 2; ++j) se += expf(r0[j] - m) + expf(r1[j] - m);
    #pragma unroll
    for (int o = 16; o; o >>= 1) se += __shfl_xor_sync(0xffffffffu, se, o);
    float ls = m + logf(se);

    float ent = 0.0f;
    #pragma unroll
    for (int j = 0; j < 2; ++j) {
        int c = 2*lane + 64*j;
        if (c < CPAD) {
            uint32_t lhp = 0, llp = 0, qhp = 0;
            if (c < CCODE) {
                float lp0 = r0[j] - ls, lp1 = r1[j] - ls;
                float q0 = expf(lp0),  q1 = expf(lp1);
                ent += q0*lp0 + q1*lp1;
                float lh0 = h_hi_f(lp0), lh1 = h_hi_f(lp1);
                lhp = pack_h2(lp0, lp1);
                llp = pack_h2(lp0 - lh0, lp1 - lh1);
                qhp = pack_h2(q0, q1);
            }
            if (rowA) { st2(rowA, KOFF_C+c, lhp); st2(rowA, KOFF_C+CPAD+c, llp); }
            st2(rowB, KOFF_C+c, qhp); st2(rowB, KOFF_C+CPAD+c, qhp);
        }
    }
    #pragma unroll
    for (int o = 16; o; o >>= 1) ent += __shfl_xor_sync(0xffffffffu, ent, o);
    if (lane == 0) *entOut = ent;
}

__global__ void __launch_bounds__(256) k_sample(const float* __restrict__ coords1,
                                                const float* __restrict__ coords2,
                                                const int* __restrict__ perms) {
    int x = blockIdx.x;
    int warp = threadIdx.x >> 5, lane = threadIdx.x & 31;
    int s = blockIdx.y * 8 + warp;
    int a = s >> 5, b = s & 31;
    if (x < 8) {
        int n = x;
        const float* crd = coords1 + (((n*SSD + b)*SSD + a) << 1);
        sample_warp(n, crd, lane,
                    g_A[n]  + (size_t)s*KTOT,
                    g_BB[n] + (size_t)s*KTOT,
                    &g_E1[n][s]);
    } else {
        int combo = x - 8;
        int i = combo & 7;
        int p = perms[combo];
        const float* crd = coords2 + (((i*SSD + b)*SSD + a) << 1);
        sample_warp(p, crd, lane,
                    (__half*)nullptr,
                    g_B2[combo] + (size_t)s*KTOT,
                    &g_E2[combo][s]);
    }
}

// ---------------- persistent fused dual-GEMM + loss + finalize ----------------
typedef __half (*Stage)[SROW];

__device__ __forceinline__ void load_stage(Stage sA, Stage sB,
                                           const __half* Ag, const __half* Bg,
                                           int k0, int tid) {
    #pragma unroll
    for (int j = 0; j < 2; ++j) {
        int chunk = tid + j*256;
        int row = chunk >> 2, q = chunk & 3;
        cp16(&sA[row][q*8], Ag + (size_t)row*KTOT + k0 + q*8);
        cp16(&sB[row][q*8], Bg + (size_t)row*KTOT + k0 + q*8);
    }
    cp_commit();
}

__device__ __forceinline__ void compute_chunk(float (*acc)[8][4],
                                              Stage sA, Stage sB,
                                              int wm, int wn, int lane) {
    int l7 = lane & 7, j = lane >> 3;
    int rAoff = ((j & 1) << 3) + l7;
    int kA8   = (j >> 1) << 3;
    int rBoff = ((j >> 1) << 3) + l7;
    int kB8   = (j & 1) << 3;
    #pragma unroll
    for (int kk = 0; kk < 32; kk += 16) {
        uint32_t a[2][4];
        #pragma unroll
        for (int mi = 0; mi < 2; ++mi) {
            uint32_t ad = (uint32_t)__cvta_generic_to_shared(&sA[wm + mi*16 + rAoff][kk + kA8]);
            ldsm4(a[mi], ad);
        }
        #pragma unroll
        for (int p = 0; p < 4; ++p) {
            uint32_t bd = (uint32_t)__cvta_generic_to_shared(&sB[wn + p*16 + rBoff][kk + kB8]);
            uint32_t bb[4];
            ldsm4(bb, bd);
            mma_f16(acc[0][2*p  ], a[0][0], a[0][1], a[0][2], a[0][3], bb[0], bb[1]);
            mma_f16(acc[0][2*p+1], a[0][0], a[0][1], a[0][2], a[0][3], bb[2], bb[3]);
            mma_f16(acc[1][2*p  ], a[1][0], a[1][1], a[1][2], a[1][3], bb[0], bb[1]);
            mma_f16(acc[1][2*p+1], a[1][0], a[1][1], a[1][2], a[1][3], bb[2], bb[3]);
        }
    }
}

__global__ void __launch_bounds__(256, 2) k_gemm(float* __restrict__ out) {
    extern __shared__ char dyn[];
    __shared__ float sh_ent[128];
    __shared__ float red[16];

    Stage sA[2], sB[2];
    #pragma unroll
    for (int b = 0; b < 2; ++b) {
        sA[b] = (Stage)(dyn + (size_t)b*STAGE_BYTES);
        sB[b] = (Stage)(dyn + (size_t)b*STAGE_BYTES + 128*SROW*2);
    }
    float* fd_s = (float*)(dyn + FD_OFF);     // [64][256] thread-private slots

    int tid = threadIdx.x;
    int warp = tid >> 5, lane = tid & 31;
    int wm = (warp & 3) * 32;
    int wn = (warp >> 2) * 64;
    int tg = lane & 3;

    float psum = 0.0f, nsum = 0.0f;

    for (int tile = blockIdx.x; tile < NTILE; tile += GRID) {
        int pair = tile >> 6;
        int rem  = tile & 63;
        int m0 = (rem >> 3) << 7;
        int n0 = (rem & 7) << 7;
        const __half *Apt, *Bpt; const float* ent;
        if (pair < 8) { Apt = g_A[pair];  Bpt = g_BB[pair]; ent = g_E1[pair]; }
        else { int c = pair - 8, i = c & 7; Apt = g_A[i]; Bpt = g_B2[c]; ent = g_E2[c]; }
        const __half* Ag = Apt + (size_t)m0*KTOT;
        const __half* Bg = Bpt + (size_t)n0*KTOT;

        __syncthreads();                      // sh_ent reuse guard
        if (tid < 128) sh_ent[tid] = ent[n0 + tid];

        float acc[2][8][4] = {};
        load_stage(sA[0], sB[0], Ag, Bg, 0, tid);
        for (int st = 0; st < NSTAGE; ++st) {
            if (st + 1 < NSTAGE) { load_stage(sA[(st+1)&1], sB[(st+1)&1], Ag, Bg, (st+1)*32, tid); cp_wait1(); }
            else                 { cp_wait0(); }
            __syncthreads();
            compute_chunk(acc, sA[st&1], sB[st&1], wm, wn, lane);
            if (st == FSTAGE - 1) {
                #pragma unroll
                for (int mi = 0; mi < 2; ++mi)
                    #pragma unroll
                    for (int ni = 0; ni < 8; ++ni)
                        #pragma unroll
                        for (int r = 0; r < 4; ++r) {
                            fd_s[(((mi*8 + ni)<<2) + r)*256 + tid] = acc[mi][ni][r];
                            acc[mi][ni][r] = 0.0f;
                        }
            }
            __syncthreads();
        }

        float lsum = 0.0f;
        #pragma unroll
        for (int ni = 0; ni < 8; ++ni) {
            float e0 = sh_ent[wn + ni*8 + 2*tg], e1 = sh_ent[wn + ni*8 + 2*tg + 1];
            #pragma unroll
            for (int mi = 0; mi < 2; ++mi) {
                #pragma unroll
                for (int r = 0; r < 4; ++r) {
                    float e  = (r & 1) ? e1 : e0;
                    float fd = fd_s[(((mi*8 + ni)<<2) + r)*256 + tid];
                    float t = e - acc[mi][ni][r] - 1.1f;
                    t = fminf(fmaxf(t, -30.0f), 30.0f);
                    float u  = __expf(t);
                    float th = __fdividef(u - 1.0f, u + 1.0f);   // tanh(t/2)
                    float d  = fd + th;
                    lsum += d * d;
                }
            }
        }
        if (pair < 8) psum += lsum; else nsum += lsum;
    }

    #pragma unroll
    for (int off = 16; off > 0; off >>= 1) {
        psum += __shfl_down_sync(0xffffffffu, psum, off);
        nsum += __shfl_down_sync(0xffffffffu, nsum, off);
    }
    if (lane == 0) { red[warp] = psum; red[8 + warp] = nsum; }
    __syncthreads();
    if (tid == 0) {
        float tp = 0.0f, tn = 0.0f;
        #pragma unroll
        for (int w = 0; w < 8; ++w) { tp += red[w]; tn += red[8 + w]; }
        if (tp != 0.0f) atomicAdd(&g_acc[0], (double)tp);
        if (tn != 0.0f) atomicAdd(&g_acc[1], (double)tn);
        __threadfence();
        int ticket = atomicAdd(&g_done, 1);
        if (ticket == GRID - 1) {
            out[0] = (float)(g_acc[0] / 8388608.0);     // 8  * 1024 * 1024
            out[1] = (float)(g_acc[1] / 41943040.0);    // 40 * 1024 * 1024
            g_done = 0;
        }
    }
}

// ---------------- launch ----------------
extern "C" void kernel_launch(void* const* d_in, const int* in_sizes, int n_in,
                              void* d_out, int out_size) {
    const float* feats   = (const float*)d_in[0];
    const float* code    = (const float*)d_in[1];
    const float* coords1 = (const float*)d_in[2];
    const float* coords2 = (const float*)d_in[3];
    const int*   perms   = (const int*)  d_in[4];
    float* out = (float*)d_out;

    cudaFuncSetAttribute(k_gemm, cudaFuncAttributeMaxDynamicSharedMemorySize, GEMM_DSMEM);

    k_tpose <<<dim3(NB, 25, 15), dim3(8, 32)>>>(feats, code);
    k_sample<<<dim3(48, 128), 256>>>(coords1, coords2, perms);
    k_gemm  <<<GRID, 256, GEMM_DSMEM>>>(out);
}